// round 7
// baseline (speedup 1.0000x reference)
#include <cuda_runtime.h>
#include <cstdint>

// Problem constants
#define B_ 64
#define L_ 512
#define P_ 64
#define A_ 16
#define F_ 80
#define D_ 512

// Scan organization
#define CSZ 8       // CTAs per cluster (column split of R)
#define NCL 16      // clusters (B_/ROWS)
#define ROWS 4      // batch rows per cluster
#define COLS 64     // columns per CTA
#define KROWS 32    // rows per warp k-slice (16 warps)
#define THREADS 512

// Scratch
__device__ float g_ci[B_ * L_ * D_];      // tanh(x@W_ci+b)
__device__ float g_part[B_ * CSZ * L_];   // per-CTA cumulative output partials

// ---- f32x2 helpers --------------------------------------------------------
__device__ __forceinline__ void fma2(unsigned long long& d, unsigned long long a, unsigned long long b) {
    asm("fma.rn.f32x2 %0, %1, %2, %0;" : "+l"(d) : "l"(a), "l"(b));
}
__device__ __forceinline__ void upk2(float& lo, float& hi, unsigned long long v) {
    asm("mov.b64 {%0,%1}, %2;" : "=f"(lo), "=f"(hi) : "l"(v));
}

// ---- mbarrier / bulk-DSMEM helpers ----------------------------------------
__device__ __forceinline__ void mbar_init(uint32_t addr, uint32_t cnt) {
    asm volatile("mbarrier.init.shared.b64 [%0], %1;" :: "r"(addr), "r"(cnt) : "memory");
}
__device__ __forceinline__ void mbar_expect_tx(uint32_t addr, uint32_t bytes) {
    asm volatile("mbarrier.arrive.expect_tx.shared.b64 _, [%0], %1;"
                 :: "r"(addr), "r"(bytes) : "memory");
}
__device__ __forceinline__ void mbar_wait_cta(uint32_t addr, uint32_t parity) {
    uint32_t done;
    asm volatile(
        "{\n\t.reg .pred p;\n\t"
        "mbarrier.try_wait.parity.acquire.cta.shared::cta.b64 p, [%1], %2;\n\t"
        "selp.b32 %0, 1, 0, p;\n\t}"
        : "=r"(done) : "r"(addr), "r"(parity) : "memory");
    if (!done) {
        asm volatile(
            "{\n\t.reg .pred P1;\n\t"
            "WL_%=:\n\t"
            "mbarrier.try_wait.parity.acquire.cta.shared::cta.b64 P1, [%0], %1, 0x989680;\n\t"
            "@P1 bra.uni WD_%=;\n\t"
            "bra.uni WL_%=;\n\t"
            "WD_%=:\n\t}"
            :: "r"(addr), "r"(parity) : "memory");
    }
}
__device__ __forceinline__ void bulk_dsmem(uint32_t dst, uint32_t src,
                                           uint32_t bytes, uint32_t mbar) {
    asm volatile(
        "cp.async.bulk.shared::cluster.shared::cta.mbarrier::complete_tx::bytes "
        "[%0], [%1], %2, [%3];"
        :: "r"(dst), "r"(src), "r"(bytes), "r"(mbar) : "memory");
}
__device__ __forceinline__ void fence_proxy_async_cta() {
    asm volatile("fence.proxy.async.shared::cta;" ::: "memory");
}

// ============================================================================
// Kernel 1: ci = tanh(x @ W_ci + b_ci)
// ============================================================================
__global__ __launch_bounds__(256)
void k_ci(const float* __restrict__ obs, const float* __restrict__ act,
          const float* __restrict__ W, const float* __restrict__ bci)
{
    __shared__ float xs[64][81];
    __shared__ float ws[80][64];

    const int tid  = threadIdx.x;
    const int row0 = blockIdx.y * 64;
    const int d0   = blockIdx.x * 64;

    for (int idx = tid; idx < 64 * 80; idx += 256) {
        int r = idx / 80, c = idx % 80;
        int blg = row0 + r;
        int b = blg >> 9, l = blg & 511;
        xs[r][c] = (c < 64) ? obs[(b * L_ + l) * P_ + c]
                            : act[(b * L_ + l) * A_ + (c - 64)];
    }
    for (int idx = tid; idx < 80 * 64; idx += 256) {
        int k = idx >> 6, d = idx & 63;
        ws[k][d] = W[k * D_ + d0 + d];
    }
    __syncthreads();

    const int tx = tid & 15, ty = tid >> 4;
    float acc[4][4] = {};
#pragma unroll
    for (int k = 0; k < 80; k++) {
        float a0 = xs[ty * 4 + 0][k];
        float a1 = xs[ty * 4 + 1][k];
        float a2 = xs[ty * 4 + 2][k];
        float a3 = xs[ty * 4 + 3][k];
        float4 bv = *(const float4*)&ws[k][tx * 4];
        acc[0][0] += a0 * bv.x; acc[0][1] += a0 * bv.y; acc[0][2] += a0 * bv.z; acc[0][3] += a0 * bv.w;
        acc[1][0] += a1 * bv.x; acc[1][1] += a1 * bv.y; acc[1][2] += a1 * bv.z; acc[1][3] += a1 * bv.w;
        acc[2][0] += a2 * bv.x; acc[2][1] += a2 * bv.y; acc[2][2] += a2 * bv.z; acc[2][3] += a2 * bv.w;
        acc[3][0] += a3 * bv.x; acc[3][1] += a3 * bv.y; acc[3][2] += a3 * bv.z; acc[3][3] += a3 * bv.w;
    }

    float bi0 = bci[d0 + tx * 4 + 0];
    float bi1 = bci[d0 + tx * 4 + 1];
    float bi2 = bci[d0 + tx * 4 + 2];
    float bi3 = bci[d0 + tx * 4 + 3];
#pragma unroll
    for (int ii = 0; ii < 4; ii++) {
        int blg = row0 + ty * 4 + ii;
        float4 o;
        o.x = tanhf(acc[ii][0] + bi0);
        o.y = tanhf(acc[ii][1] + bi1);
        o.z = tanhf(acc[ii][2] + bi2);
        o.w = tanhf(acc[ii][3] + bi3);
        *(float4*)&g_ci[blg * D_ + d0 + tx * 4] = o;
    }
}

// ============================================================================
// Kernel 2: the scan.
//  - R column-pairs pre-packed in 64-bit registers (no per-iter packing)
//  - h stored DUPLICATED in smem: row i = (h0,h0,h1,h1,h2,h2,h3,h3), 32 B
//  - matvec iter: 2x LDS.128 + 4x FFMA2 = 6 issues (FMA-pipe-bound)
//  - per-(buffer,source) mbarriers: warp-level waits overlap DMA flight
//
// SMEM (floats):
//   hbuf2 [0, 12288)       3 x 512 x 8   (duplicated h)
//   pbuf  [12288, 16384)   512 x 8
//   hsta2 [16384, 17408)   2 x 512       (duplicated DMA source)
//   bias  [17408, 17472)
//   wsl   [17472, 17536)
//   osum  [17536, 17568)
//   mbar  @ byte 70272: 3 bufs x 8 sources x 8 B = 192 B
// ============================================================================
#define HBUF_OFF  0
#define PBUF_OFF  12288
#define HSTA_OFF  16384
#define BIAS_OFF  17408
#define WSL_OFF   17472
#define OSUM_OFF  17536
#define MBAR_BYTE 70272
#define SMEM_BYTES (MBAR_BYTE + 192)

#define SLICE_BYTES 2048                  // 64 rows x 32 B (duplicated)
#define HROW 8                            // floats per duplicated h row

extern __shared__ float smem_f[];

__global__ void __cluster_dims__(CSZ, 1, 1) __launch_bounds__(THREADS, 1)
k_scan(const float* __restrict__ R, const float* __restrict__ b_ig,
       const float* __restrict__ W_out)
{
    float* hbuf = smem_f + HBUF_OFF;
    float* pbuf = smem_f + PBUF_OFF;
    float* hsta = smem_f + HSTA_OFF;
    float* bias = smem_f + BIAS_OFF;
    float* wsl  = smem_f + WSL_OFF;
    float* osum = smem_f + OSUM_OFF;

    const uint32_t smem_u32 = (uint32_t)__cvta_generic_to_shared(smem_f);

    const int tid = threadIdx.x;
    const int c   = blockIdx.x;          // cluster rank / column slice
    const int b0  = blockIdx.y * ROWS;
    const int j0  = c * COLS;

    const int ks   = tid >> 5;           // warp = k-slice (0..15)
    const int jp   = tid & 31;           // column pair (cols 2jp, 2jp+1)
    const int lane = tid & 31;
    const int src  = ks >> 1;            // source CTA feeding this warp's rows
    const int jj = tid >> 2;             // reduce mapping (tid<256)
    const int bb = tid & 3;

    // ---- R column-pairs into packed 64-bit registers ----
    unsigned long long rp[KROWS];
    {
        const float* rg = R + j0 + 2 * jp;
#pragma unroll
        for (int ii = 0; ii < KROWS; ii++)
            rp[ii] = *(const unsigned long long*)(rg + (ks * KROWS + ii) * D_);
    }

    // ---- init smem ----
    for (int idx = tid; idx < 3 * D_ * HROW; idx += THREADS) hbuf[idx] = 0.0f;
    if (tid < COLS) {
        bias[tid] = b_ig[j0 + tid];
        wsl[tid]  = W_out[j0 + tid];
    }
    if (tid < 24) {   // 3 buffers x 8 sources
        mbar_init(smem_u32 + MBAR_BYTE + tid * 8, 1);
    }
    __syncthreads();
    if (tid < 24) {
        mbar_expect_tx(smem_u32 + MBAR_BYTE + tid * 8, SLICE_BYTES);
    }
    __syncthreads();
    asm volatile("barrier.cluster.arrive.aligned;" ::: "memory");
    asm volatile("barrier.cluster.wait.aligned;"   ::: "memory");

    // Peer smem bases
    uint32_t peer_base[CSZ];
#pragma unroll
    for (int p = 0; p < CSZ; p++) {
        asm volatile("mapa.shared::cluster.u32 %0, %1, %2;"
                     : "=r"(peer_base[p]) : "r"(smem_u32), "r"(p));
    }

    float racc = 0.0f;
    int cur = 0;
    uint32_t phases = 0;   // bit b = next wait parity for buffer b

    for (int t = 0; t < L_; t++) {
        const int nxt = (cur == 2) ? 0 : cur + 1;

        // prefetch ci (consumed after matvec)
        float civ = 0.0f;
        if (tid < 256)
            civ = __ldg(&g_ci[((b0 + bb) * L_ + t) * D_ + j0 + jj]);

        // per-warp wait: only this warp's source slice must have arrived
        if (t > 0) {
            uint32_t mb = smem_u32 + (uint32_t)(MBAR_BYTE + (cur * CSZ + src) * 8);
            mbar_wait_cta(mb, (phases >> cur) & 1u);
            phases ^= (1u << cur);
            // re-post expect for this barrier's next round (one warp per barrier)
            if (lane == 0 && (ks & 1) == 0)
                mbar_expect_tx(mb, SLICE_BYTES);
        }

        // ---- matvec: packed R regs x duplicated-h smem ----
        {
            const ulonglong2* hrow =
                (const ulonglong2*)(hbuf + cur * (D_ * HROW) + ks * KROWS * HROW);
            unsigned long long a0 = 0, a1 = 0, a2 = 0, a3 = 0;
#pragma unroll
            for (int ii = 0; ii < KROWS; ii++) {
                ulonglong2 h01 = hrow[2 * ii];       // (h0,h0),(h1,h1)
                ulonglong2 h23 = hrow[2 * ii + 1];   // (h2,h2),(h3,h3)
                fma2(a0, rp[ii], h01.x);
                fma2(a1, rp[ii], h01.y);
                fma2(a2, rp[ii], h23.x);
                fma2(a3, rp[ii], h23.y);
            }
            // a_b = (z[2jp][b], z[2jp+1][b])
            float4 q0, q1;
            upk2(q0.x, q1.x, a0);
            upk2(q0.y, q1.y, a1);
            upk2(q0.z, q1.z, a2);
            upk2(q0.w, q1.w, a3);
            float* pb = pbuf + (ks * 32 + jp) * 8;
            *(float4*)(pb)     = q0;   // col 2jp,   b0..b3
            *(float4*)(pb + 4) = q1;   // col 2jp+1, b0..b3
        }
        __syncthreads();

        const float* hc = hbuf + cur * (D_ * HROW);

        // ---- reduce + gate + update ----
        if (tid < 256) {
            float z = bias[jj];
#pragma unroll
            for (int s = 0; s < 16; s++) z += pbuf[s * 256 + tid];
            float ig = 1.0f / (1.0f + __expf(-z));
            float u  = civ * ig;
            float hval = hc[(j0 + jj) * HROW + bb * 2] + u;
            ((float2*)hsta)[(t & 1) * 256 + tid] = make_float2(hval, hval);

            float pp = u * wsl[jj];
            pp += __shfl_xor_sync(0xFFFFFFFF, pp, 4);
            pp += __shfl_xor_sync(0xFFFFFFFF, pp, 8);
            pp += __shfl_xor_sync(0xFFFFFFFF, pp, 16);
            if ((tid & 31) < 4)
                osum[(tid >> 5) * 4 + bb] = pp;
        }
        __syncthreads();

        // ---- DMA broadcast h(t+1): 8 threads, one bulk copy per peer ----
        if (t + 1 < L_ && tid < CSZ) {
            fence_proxy_async_cta();
            uint32_t src_a = smem_u32 + (uint32_t)(HSTA_OFF + (t & 1) * 512) * 4u;
            uint32_t doff  = (uint32_t)(HBUF_OFF + nxt * (D_ * HROW)) * 4u
                           + (uint32_t)(c * SLICE_BYTES);
            uint32_t moff  = (uint32_t)(MBAR_BYTE + (nxt * CSZ + c) * 8);
            bulk_dsmem(peer_base[tid] + doff, src_a, SLICE_BYTES,
                       peer_base[tid] + moff);
        }

        // ---- cumulative output partial ----
        if (tid < 4) {
            float s = 0.0f;
#pragma unroll
            for (int w = 0; w < 8; w++) s += osum[w * 4 + tid];
            racc += s;
            g_part[(b0 + tid) * (CSZ * L_) + c * L_ + t] = racc;
        }

        cur = nxt;
    }

    asm volatile("barrier.cluster.arrive.aligned;" ::: "memory");
    asm volatile("barrier.cluster.wait.aligned;"   ::: "memory");
}

// ============================================================================
// Kernel 3: out[b,t] = b_out + sum_c g_part[b][c][t]
// ============================================================================
__global__ __launch_bounds__(256)
void k_out(const float* __restrict__ b_out, float* __restrict__ out)
{
    int i = blockIdx.x * 256 + threadIdx.x;
    int b = i >> 9, t = i & 511;
    float s = b_out[0];
#pragma unroll
    for (int cc = 0; cc < CSZ; cc++) s += g_part[b * (CSZ * L_) + cc * L_ + t];
    out[i] = s;
}

// ============================================================================
extern "C" void kernel_launch(void* const* d_in, const int* in_sizes, int n_in,
                              void* d_out, int out_size)
{
    const float* obs  = (const float*)d_in[0];
    const float* act  = (const float*)d_in[1];
    const float* W_ci = (const float*)d_in[2];
    const float* b_ci = (const float*)d_in[3];
    const float* R    = (const float*)d_in[4];
    const float* bg   = (const float*)d_in[5];
    const float* W_o  = (const float*)d_in[6];
    const float* b_o  = (const float*)d_in[7];
    float* out = (float*)d_out;

    k_ci<<<dim3(8, 512), 256>>>(obs, act, W_ci, b_ci);

    cudaFuncSetAttribute(k_scan, cudaFuncAttributeMaxDynamicSharedMemorySize, SMEM_BYTES);
    k_scan<<<dim3(CSZ, NCL), THREADS, SMEM_BYTES>>>(R, bg, W_o);

    k_out<<<128, 256>>>(b_o, out);
}